// round 3
// baseline (speedup 1.0000x reference)
#include <cuda_runtime.h>
#include <mma.h>

using namespace nvcuda;

// Problem constants (fixed by reference)
#define Bc 4
#define Hc 16
#define Sc 2048
#define Dc 128

// Tiling
#define TQ 64
#define TK 64
#define THREADS 256
#define QLD 136   // row stride (floats) for Q/K/V smem tiles (128 + 8 pad)
#define PLD 72    // row stride for P tile (64 + 8 pad)

// smem (floats): Qs[64*136]  Ks[2][64*136]  Vs[2][64*136]  Ps[64*72]  lrow[64]
#define TILE_F (TQ * QLD)
#define SMEM_FLOATS (5 * TILE_F + TQ * PLD + TQ)
#define SMEM_BYTES (SMEM_FLOATS * 4)

__device__ __forceinline__ void cp_async16(float* smem_dst, const float* gmem_src) {
    unsigned saddr = (unsigned)__cvta_generic_to_shared(smem_dst);
    asm volatile("cp.async.cg.shared.global [%0], [%1], 16;\n" ::"r"(saddr), "l"(gmem_src));
}
__device__ __forceinline__ void cp_commit() {
    asm volatile("cp.async.commit_group;\n");
}
__device__ __forceinline__ void cp_wait_all() {
    asm volatile("cp.async.wait_group 0;\n");
}

__global__ __launch_bounds__(THREADS, 1)
void attn_main_kernel(const float* __restrict__ qg,
                      const float* __restrict__ kg,
                      const float* __restrict__ vg,
                      const float* __restrict__ mg,
                      float* __restrict__ outg,
                      float* __restrict__ attng) {
    extern __shared__ float sm[];
    float* Qs   = sm;                       // [64 x 136]
    float* Ks   = Qs + TILE_F;              // [2][64 x 136]
    float* Vs   = Ks + 2 * TILE_F;          // [2][64 x 136]
    float* Ps   = Vs + 2 * TILE_F;          // [64 x 72]
    float* lrow = Ps + TQ * PLD;            // [64]

    const int h  = blockIdx.x;   // fastest: mask slice reused across heads via L2
    const int qt = blockIdx.y;
    const int b  = blockIdx.z;
    const int tid  = threadIdx.x;
    const int warp = tid >> 5;
    const int q0   = qt * TQ;

    const long long bh = (long long)b * Hc + h;
    const float* qptr  = qg + (bh * Sc + q0) * (long long)Dc;
    const float* kbase = kg + bh * Sc * (long long)Dc;
    const float* vbase = vg + bh * Sc * (long long)Dc;
    const float* mbase = mg + ((long long)b * Sc + q0) * (long long)Sc;
    float* attnbase = attng ? (attng + (bh * Sc + q0) * (long long)Sc) : nullptr;

    // Load Q tile (64 x 128), pre-rounded to tf32 so fragments need no conversion
    for (int idx = tid * 4; idx < TQ * Dc; idx += THREADS * 4) {
        int r = idx >> 7, c = idx & 127;
        float4 val = *(const float4*)(qptr + (long long)r * Dc + c);
        val.x = wmma::__float_to_tf32(val.x);
        val.y = wmma::__float_to_tf32(val.y);
        val.z = wmma::__float_to_tf32(val.z);
        val.w = wmma::__float_to_tf32(val.w);
        *(float4*)(Qs + r * QLD + c) = val;
    }
    if (tid < TQ) lrow[tid] = 0.0f;

    // Persistent PV accumulators: warp -> row tile ti, col tiles jb..jb+3
    const int ti  = warp >> 1;         // 0..3 (16-row tile of the 64 queries)
    const int tj2 = (warp & 1) * 2;    // scores col tiles: tj2, tj2+1
    const int jb  = (warp & 1) * 4;    // PV col tiles: jb..jb+3 (of 8)

    wmma::fragment<wmma::accumulator, 16, 16, 8, float> Oacc[4];
    #pragma unroll
    for (int j = 0; j < 4; ++j) wmma::fill_fragment(Oacc[j], 0.0f);

    // ---- Prologue: async prefetch of K/V tile 0 into buffer 0 ----
    {
        const float* kp = kbase;
        const float* vp = vbase;
        #pragma unroll
        for (int i = 0; i < 8; ++i) {
            int fid = tid + i * THREADS;          // 0..2047 float4 slots
            int r = fid >> 5, c = (fid & 31) * 4; // 32 float4 per 128-float row
            cp_async16(Ks + r * QLD + c, kp + r * Dc + c);
            cp_async16(Vs + r * QLD + c, vp + r * Dc + c);
        }
        cp_commit();
    }

    for (int kt = 0; kt < Sc / TK; ++kt) {
        const int cur = kt & 1;
        const int nxt = cur ^ 1;

        cp_wait_all();
        __syncthreads();  // cur buffers visible; prev iter's PV reads of nxt done

        // Prefetch next K/V tile into the other buffer
        if (kt + 1 < Sc / TK) {
            const float* kp = kbase + (long long)(kt + 1) * TK * Dc;
            const float* vp = vbase + (long long)(kt + 1) * TK * Dc;
            #pragma unroll
            for (int i = 0; i < 8; ++i) {
                int fid = tid + i * THREADS;
                int r = fid >> 5, c = (fid & 31) * 4;
                cp_async16(Ks + nxt * TILE_F + r * QLD + c, kp + r * Dc + c);
                cp_async16(Vs + nxt * TILE_F + r * QLD + c, vp + r * Dc + c);
            }
            cp_commit();
        }

        const float* Kc = Ks + cur * TILE_F;
        const float* Vc = Vs + cur * TILE_F;

        // ---- Scores: S = Q * K^T (tf32 wmma; no per-fragment conversion) ----
        wmma::fragment<wmma::accumulator, 16, 16, 8, float> Sacc[2];
        wmma::fill_fragment(Sacc[0], 0.0f);
        wmma::fill_fragment(Sacc[1], 0.0f);
        #pragma unroll 4
        for (int k8 = 0; k8 < Dc / 8; ++k8) {
            wmma::fragment<wmma::matrix_a, 16, 16, 8, wmma::precision::tf32, wmma::row_major> af;
            wmma::load_matrix_sync(af, Qs + ti * 16 * QLD + k8 * 8, QLD);
            #pragma unroll
            for (int jj = 0; jj < 2; ++jj) {
                wmma::fragment<wmma::matrix_b, 16, 16, 8, wmma::precision::tf32, wmma::col_major> bf;
                wmma::load_matrix_sync(bf, Kc + (tj2 + jj) * 16 * QLD + k8 * 8, QLD);
                wmma::mma_sync(Sacc[jj], af, bf, Sacc[jj]);
            }
        }
        wmma::store_matrix_sync(Ps + ti * 16 * PLD + tj2 * 16, Sacc[0], PLD, wmma::mem_row_major);
        wmma::store_matrix_sync(Ps + ti * 16 * PLD + (tj2 + 1) * 16, Sacc[1], PLD, wmma::mem_row_major);
        __syncthreads();

        // ---- Elementwise: p = mask ? 0 : exp(s/128) via FMA polynomial ----
        {
            const int r  = tid >> 2;           // query row within tile
            const int c0 = (tid & 3) * 16;     // 16-col segment
            const float* mrow = mbase + (long long)r * Sc + kt * TK;
            float lsum = 0.0f;
            #pragma unroll
            for (int cc = 0; cc < 4; ++cc) {
                int c = c0 + cc * 4;
                float4 s4 = *(float4*)(Ps + r * PLD + c);
                float4 m4 = *(const float4*)(mrow + c);
                float4 p;
                #pragma unroll
                for (int e = 0; e < 4; ++e) {
                    float x = ((&s4.x)[e]) * 0.0078125f;
                    // degree-6 Taylor: rel err < 3e-6 for |x| <= 0.5
                    float pe = 1.388888889e-3f;                // 1/720
                    pe = fmaf(pe, x, 8.333333333e-3f);          // 1/120
                    pe = fmaf(pe, x, 4.166666667e-2f);          // 1/24
                    pe = fmaf(pe, x, 1.666666667e-1f);          // 1/6
                    pe = fmaf(pe, x, 0.5f);
                    pe = fmaf(pe, x, 1.0f);
                    pe = fmaf(pe, x, 1.0f);
                    if (fabsf(x) > 0.5f) pe = __expf(x);        // ~never taken
                    (&p.x)[e] = ((&m4.x)[e] != 0.0f) ? 0.0f : pe;
                }
                *(float4*)(Ps + r * PLD + c) = p;
                if (attnbase)
                    *(float4*)(attnbase + (long long)r * Sc + kt * TK + c) = p;
                lsum += p.x + p.y + p.z + p.w;
            }
            lsum += __shfl_xor_sync(0xffffffffu, lsum, 1);
            lsum += __shfl_xor_sync(0xffffffffu, lsum, 2);
            if ((tid & 3) == 0) lrow[r] += lsum;
        }
        __syncthreads();

        // ---- PV: O += P * V (tf32 wmma) ----
        #pragma unroll 2
        for (int k8 = 0; k8 < TK / 8; ++k8) {
            wmma::fragment<wmma::matrix_a, 16, 16, 8, wmma::precision::tf32, wmma::row_major> af;
            wmma::load_matrix_sync(af, Ps + ti * 16 * PLD + k8 * 8, PLD);
            #pragma unroll
            for (int jj = 0; jj < 4; ++jj) {
                wmma::fragment<wmma::matrix_b, 16, 16, 8, wmma::precision::tf32, wmma::row_major> bf;
                wmma::load_matrix_sync(bf, Vc + k8 * 8 * QLD + (jb + jj) * 16, QLD);
                wmma::mma_sync(Oacc[jj], af, bf, Oacc[jj]);
            }
        }
    }

    __syncthreads();
    // Stage O into smem (reuse Qs), then scaled write to gmem
    #pragma unroll
    for (int jj = 0; jj < 4; ++jj)
        wmma::store_matrix_sync(Qs + ti * 16 * QLD + (jb + jj) * 16, Oacc[jj], QLD,
                                wmma::mem_row_major);
    __syncthreads();

    {
        const int r  = tid >> 2;
        const int c0 = (tid & 3) * 32;
        const float inv = 1.0f / lrow[r];
        float* orow = outg + (bh * Sc + q0 + r) * (long long)Dc;
        #pragma unroll
        for (int cc = 0; cc < 8; ++cc) {
            int c = c0 + cc * 4;
            float4 o4 = *(float4*)(Qs + r * QLD + c);
            o4.x *= inv; o4.y *= inv; o4.z *= inv; o4.w *= inv;
            *(float4*)(orow + c) = o4;
        }
    }
}

// Kernel 2: normalize each attn row in place (re-derives the row sum).
// Measured 88.5% DRAM / 7.0 TB/s -> at roofline, leave as is.
__global__ __launch_bounds__(256, 8)
void attn_norm_kernel(float* __restrict__ attn) {
    const long long row = blockIdx.x;
    float4* rp = (float4*)(attn + row * (long long)Sc);
    const int t = threadIdx.x;

    float4 a = rp[t];
    float4 b = rp[t + 256];
    float s = a.x + a.y + a.z + a.w + b.x + b.y + b.z + b.w;
    #pragma unroll
    for (int o = 16; o > 0; o >>= 1) s += __shfl_xor_sync(0xffffffffu, s, o);

    __shared__ float red[8];
    if ((t & 31) == 0) red[t >> 5] = s;
    __syncthreads();
    float tot = red[0] + red[1] + red[2] + red[3] + red[4] + red[5] + red[6] + red[7];
    float inv = 1.0f / tot;

    a.x *= inv; a.y *= inv; a.z *= inv; a.w *= inv;
    b.x *= inv; b.y *= inv; b.z *= inv; b.w *= inv;
    rp[t] = a;
    rp[t + 256] = b;
}

extern "C" void kernel_launch(void* const* d_in, const int* in_sizes, int n_in,
                              void* d_out, int out_size) {
    const float* q = (const float*)d_in[0];
    const float* k = (const float*)d_in[1];
    const float* v = (const float*)d_in[2];
    const float* m = (const float*)d_in[3];
    float* out = (float*)d_out;

    const long long OUT_ELE = (long long)Bc * Hc * Sc * Dc;  // 16,777,216
    float* attn = ((long long)out_size > OUT_ELE) ? (out + OUT_ELE) : nullptr;

    cudaFuncSetAttribute(attn_main_kernel,
                         cudaFuncAttributeMaxDynamicSharedMemorySize, SMEM_BYTES);

    dim3 grid1(Hc, Sc / TQ, Bc);  // h fastest -> mask L2 reuse across heads
    attn_main_kernel<<<grid1, THREADS, SMEM_BYTES>>>(q, k, v, m, out, attn);

    if (attn) {
        attn_norm_kernel<<<(long long)Bc * Hc * Sc, 256>>>(attn);
    }
}

// round 4
// speedup vs baseline: 1.9972x; 1.9972x over previous
#include <cuda_runtime.h>
#include <cuda_fp16.h>
#include <mma.h>

using namespace nvcuda;

// Problem constants
#define Bc 4
#define Hc 16
#define Sc 2048
#define Dc 128

// Tiling
#define TQ 64
#define TK 64
#define THREADS 512          // 16 warps
#define LDH  136             // half stride for Q/K/V tiles (128 + 8)
#define PLDF 68              // float stride for score tile (64 + 4)
#define PLDH 72              // half stride for P tile (64 + 8)
#define OLDF 132             // float stride for O staging (reuses K region)

// smem layout (bytes)
#define QH_OFF   0
#define KH_OFF   (QH_OFF + TQ * LDH * 2)
#define VH_OFF   (KH_OFF + 2 * TK * LDH * 2)
#define PSF_OFF  (VH_OFF + 2 * TK * LDH * 2)
#define PSH_OFF  (PSF_OFF + TQ * PLDF * 4)
#define LROW_OFF (PSH_OFF + TQ * PLDH * 2)
#define SMEM_BYTES (LROW_OFF + TQ * 4)   // 113,920 B

__global__ __launch_bounds__(THREADS, 1)
void attn_main_kernel(const float* __restrict__ qg,
                      const float* __restrict__ kg,
                      const float* __restrict__ vg,
                      const float* __restrict__ mg,
                      float* __restrict__ outg,
                      float* __restrict__ attng) {
    extern __shared__ char sm[];
    __half* Qh   = (__half*)(sm + QH_OFF);
    __half* Kh   = (__half*)(sm + KH_OFF);   // [2][64 x LDH]
    __half* Vh   = (__half*)(sm + VH_OFF);   // [2][64 x LDH]
    float*  Psf  = (float*)(sm + PSF_OFF);   // [64 x PLDF]
    __half* Psh  = (__half*)(sm + PSH_OFF);  // [64 x PLDH]
    float*  lrow = (float*)(sm + LROW_OFF);  // [64]

    const int h  = blockIdx.x;   // fastest: mask slice L2-reused across heads
    const int qt = blockIdx.y;
    const int b  = blockIdx.z;
    const int tid  = threadIdx.x;
    const int warp = tid >> 5;
    const int q0   = qt * TQ;

    const long long bh = (long long)b * Hc + h;
    const float* qptr  = qg + (bh * Sc + q0) * (long long)Dc;
    const float* kbase = kg + bh * Sc * (long long)Dc;
    const float* vbase = vg + bh * Sc * (long long)Dc;
    const float* mbase = mg + ((long long)b * Sc + q0) * (long long)Sc;
    float* attnbase = attng ? (attng + (bh * Sc + q0) * (long long)Sc) : nullptr;

    // ---- Load Q (64x128 fp32 -> fp16 RN) ----
    #pragma unroll
    for (int i = 0; i < 4; ++i) {
        int fid = tid + i * THREADS;       // 0..2047 float4 slots
        int r = fid >> 5, c = (fid & 31) * 4;
        float4 v = *(const float4*)(qptr + (long long)r * Dc + c);
        __half2 h01 = __floats2half2_rn(v.x, v.y);
        __half2 h23 = __floats2half2_rn(v.z, v.w);
        uint2 u; u.x = *(unsigned*)&h01; u.y = *(unsigned*)&h23;
        *(uint2*)(Qh + r * LDH + c) = u;
    }
    if (tid < TQ) lrow[tid] = 0.0f;

    // Warp tiles: scores warp w -> (ti, tj) 16x16;  PV warp w -> rows ti, 2 col tiles
    const int ti = warp >> 2;        // 0..3
    const int tj = warp & 3;         // 0..3

    wmma::fragment<wmma::accumulator, 16, 16, 16, float> Oacc[2];
    wmma::fill_fragment(Oacc[0], 0.0f);
    wmma::fill_fragment(Oacc[1], 0.0f);

    // ---- Register-staged K/V pipeline ----
    float4 kreg[4], vreg[4];
    {
        const float* kp = kbase;
        const float* vp = vbase;
        #pragma unroll
        for (int i = 0; i < 4; ++i) {
            int fid = tid + i * THREADS;
            int r = fid >> 5, c = (fid & 31) * 4;
            kreg[i] = *(const float4*)(kp + (long long)r * Dc + c);
            vreg[i] = *(const float4*)(vp + (long long)r * Dc + c);
        }
    }

    const int NKT = Sc / TK;
    for (int kt = 0; kt < NKT; ++kt) {
        const int cur = kt & 1;

        // Store staged K/V (fp32 -> fp16 RN) into current buffers
        #pragma unroll
        for (int i = 0; i < 4; ++i) {
            int fid = tid + i * THREADS;
            int r = fid >> 5, c = (fid & 31) * 4;
            __half2 a = __floats2half2_rn(kreg[i].x, kreg[i].y);
            __half2 bb = __floats2half2_rn(kreg[i].z, kreg[i].w);
            uint2 u; u.x = *(unsigned*)&a; u.y = *(unsigned*)&bb;
            *(uint2*)(Kh + cur * TK * LDH + r * LDH + c) = u;
            a  = __floats2half2_rn(vreg[i].x, vreg[i].y);
            bb = __floats2half2_rn(vreg[i].z, vreg[i].w);
            u.x = *(unsigned*)&a; u.y = *(unsigned*)&bb;
            *(uint2*)(Vh + cur * TK * LDH + r * LDH + c) = u;
        }
        __syncthreads();

        // Prefetch next K/V into registers (hidden behind this iteration)
        if (kt + 1 < NKT) {
            const float* kp = kbase + (long long)(kt + 1) * TK * Dc;
            const float* vp = vbase + (long long)(kt + 1) * TK * Dc;
            #pragma unroll
            for (int i = 0; i < 4; ++i) {
                int fid = tid + i * THREADS;
                int r = fid >> 5, c = (fid & 31) * 4;
                kreg[i] = *(const float4*)(kp + (long long)r * Dc + c);
                vreg[i] = *(const float4*)(vp + (long long)r * Dc + c);
            }
        }

        const __half* Kc = Kh + cur * TK * LDH;
        const __half* Vc = Vh + cur * TK * LDH;

        // ---- Scores: S = Q * K^T (fp16 wmma, fp32 acc) ----
        {
            wmma::fragment<wmma::accumulator, 16, 16, 16, float> Sacc;
            wmma::fill_fragment(Sacc, 0.0f);
            #pragma unroll
            for (int k = 0; k < Dc / 16; ++k) {
                wmma::fragment<wmma::matrix_a, 16, 16, 16, __half, wmma::row_major> af;
                wmma::fragment<wmma::matrix_b, 16, 16, 16, __half, wmma::col_major> bf;
                wmma::load_matrix_sync(af, Qh + ti * 16 * LDH + k * 16, LDH);
                wmma::load_matrix_sync(bf, Kc + tj * 16 * LDH + k * 16, LDH);
                wmma::mma_sync(Sacc, af, bf, Sacc);
            }
            wmma::store_matrix_sync(Psf + ti * 16 * PLDF + tj * 16, Sacc, PLDF,
                                    wmma::mem_row_major);
        }
        __syncthreads();

        // ---- Elementwise: p = mask ? 0 : exp(s/128); attn write; rowsum; P->fp16 ----
        {
            const int r  = tid >> 3;          // 0..63
            const int c0 = (tid & 7) * 8;     // 8 cols per thread
            const float* mrow = mbase + (long long)r * Sc + kt * TK + c0;
            float* arow = attnbase ? attnbase + (long long)r * Sc + kt * TK + c0 : nullptr;
            const float* srow = Psf + r * PLDF + c0;
            float lsum = 0.0f;
            __half2 ph[4];
            #pragma unroll
            for (int cc = 0; cc < 2; ++cc) {
                float4 s4 = *(const float4*)(srow + cc * 4);
                float4 m4 = *(const float4*)(mrow + cc * 4);
                float4 p;
                #pragma unroll
                for (int e = 0; e < 4; ++e) {
                    float x = ((&s4.x)[e]) * 0.0078125f;
                    float pe = 1.388888889e-3f;                 // 1/720
                    pe = fmaf(pe, x, 8.333333333e-3f);           // 1/120
                    pe = fmaf(pe, x, 4.166666667e-2f);           // 1/24
                    pe = fmaf(pe, x, 1.666666667e-1f);           // 1/6
                    pe = fmaf(pe, x, 0.5f);
                    pe = fmaf(pe, x, 1.0f);
                    pe = fmaf(pe, x, 1.0f);
                    if (fabsf(x) > 0.5f) pe = __expf(x);         // ~never taken
                    (&p.x)[e] = ((&m4.x)[e] != 0.0f) ? 0.0f : pe;
                }
                if (arow) *(float4*)(arow + cc * 4) = p;
                lsum += p.x + p.y + p.z + p.w;
                ph[cc * 2 + 0] = __floats2half2_rn(p.x, p.y);
                ph[cc * 2 + 1] = __floats2half2_rn(p.z, p.w);
            }
            uint4 u;
            u.x = *(unsigned*)&ph[0]; u.y = *(unsigned*)&ph[1];
            u.z = *(unsigned*)&ph[2]; u.w = *(unsigned*)&ph[3];
            *(uint4*)(Psh + r * PLDH + c0) = u;

            lsum += __shfl_xor_sync(0xffffffffu, lsum, 1);
            lsum += __shfl_xor_sync(0xffffffffu, lsum, 2);
            lsum += __shfl_xor_sync(0xffffffffu, lsum, 4);
            if ((tid & 7) == 0) lrow[r] += lsum;
        }
        __syncthreads();

        // ---- PV: O += P * V (fp16 wmma); warp covers rows ti, cols (tj*2..tj*2+1) ----
        #pragma unroll
        for (int k = 0; k < TK / 16; ++k) {
            wmma::fragment<wmma::matrix_a, 16, 16, 16, __half, wmma::row_major> af;
            wmma::load_matrix_sync(af, Psh + ti * 16 * PLDH + k * 16, PLDH);
            #pragma unroll
            for (int jj = 0; jj < 2; ++jj) {
                wmma::fragment<wmma::matrix_b, 16, 16, 16, __half, wmma::row_major> bf;
                wmma::load_matrix_sync(bf, Vc + k * 16 * LDH + (tj * 2 + jj) * 16, LDH);
                wmma::mma_sync(Oacc[jj], af, bf, Oacc[jj]);
            }
        }
        // no trailing sync: next iter writes the other K/V buffer; top sync covers visibility
    }

    __syncthreads();
    // Stage O (fp32) into the K region, then normalized write
    float* Of = (float*)(sm + KH_OFF);   // 64 x OLDF
    #pragma unroll
    for (int jj = 0; jj < 2; ++jj)
        wmma::store_matrix_sync(Of + ti * 16 * OLDF + (tj * 2 + jj) * 16, Oacc[jj],
                                OLDF, wmma::mem_row_major);
    __syncthreads();

    {
        const int r  = tid >> 3;
        const int c0 = (tid & 7) * 16;
        const float inv = 1.0f / lrow[r];
        float* orow = outg + (bh * Sc + q0 + r) * (long long)Dc;
        #pragma unroll
        for (int cc = 0; cc < 4; ++cc) {
            int c = c0 + cc * 4;
            float4 o4 = *(const float4*)(Of + r * OLDF + c);
            o4.x *= inv; o4.y *= inv; o4.z *= inv; o4.w *= inv;
            *(float4*)(orow + c) = o4;
        }
    }
}

// Kernel 2: normalize each attn row in place. Measured 87.7% DRAM -> at roofline.
__global__ __launch_bounds__(256, 8)
void attn_norm_kernel(float* __restrict__ attn) {
    const long long row = blockIdx.x;
    float4* rp = (float4*)(attn + row * (long long)Sc);
    const int t = threadIdx.x;

    float4 a = rp[t];
    float4 b = rp[t + 256];
    float s = a.x + a.y + a.z + a.w + b.x + b.y + b.z + b.w;
    #pragma unroll
    for (int o = 16; o > 0; o >>= 1) s += __shfl_xor_sync(0xffffffffu, s, o);

    __shared__ float red[8];
    if ((t & 31) == 0) red[t >> 5] = s;
    __syncthreads();
    float tot = red[0] + red[1] + red[2] + red[3] + red[4] + red[5] + red[6] + red[7];
    float inv = 1.0f / tot;

    a.x *= inv; a.y *= inv; a.z *= inv; a.w *= inv;
    b.x *= inv; b.y *= inv; b.z *= inv; b.w *= inv;
    rp[t] = a;
    rp[t + 256] = b;
}

extern "C" void kernel_launch(void* const* d_in, const int* in_sizes, int n_in,
                              void* d_out, int out_size) {
    const float* q = (const float*)d_in[0];
    const float* k = (const float*)d_in[1];
    const float* v = (const float*)d_in[2];
    const float* m = (const float*)d_in[3];
    float* out = (float*)d_out;

    const long long OUT_ELE = (long long)Bc * Hc * Sc * Dc;  // 16,777,216
    float* attn = ((long long)out_size > OUT_ELE) ? (out + OUT_ELE) : nullptr;

    cudaFuncSetAttribute(attn_main_kernel,
                         cudaFuncAttributeMaxDynamicSharedMemorySize, SMEM_BYTES);

    dim3 grid1(Hc, Sc / TQ, Bc);  // h fastest -> mask L2 reuse across heads
    attn_main_kernel<<<grid1, THREADS, SMEM_BYTES>>>(q, k, v, m, out, attn);

    if (attn) {
        attn_norm_kernel<<<(long long)Bc * Hc * Sc, 256>>>(attn);
    }
}

// round 6
// speedup vs baseline: 2.0840x; 1.0434x over previous
#include <cuda_runtime.h>
#include <cuda_fp16.h>
#include <mma.h>

using namespace nvcuda;

// Problem constants
#define Bc 4
#define Hc 16
#define Sc 2048
#define Dc 128

// Tiling
#define TQ 64
#define TK 64
#define THREADS 512          // 16 warps
#define LDH  136             // half stride for Q/K/V tiles (128 + 8)
#define PLDF 68              // float stride for score tile (64 + 4)
#define PLDH 72              // half stride for P tile (64 + 8)
#define MLD  64              // float stride for mask tile
#define OLDF 132             // float stride for O staging (reuses K+V region)

// smem layout (bytes) — single-buffered K/V, double-buffered mask
#define QH_OFF   0
#define KH_OFF   (QH_OFF + TQ * LDH * 2)          // 17408
#define VH_OFF   (KH_OFF + TK * LDH * 2)          // 17408
#define PSF_OFF  (VH_OFF + TK * LDH * 2)          // 17408
#define PSH_OFF  (PSF_OFF + TQ * PLDF * 4)        // 17408
#define MS_OFF   (PSH_OFF + TQ * PLDH * 2)        // 9216
#define LROW_OFF (MS_OFF + 2 * TQ * MLD * 4)      // 32768
#define SMEM_BYTES (LROW_OFF + TQ * 4)            // 111,872 B -> 2 CTAs/SM

__device__ __forceinline__ void cp_async16(void* smem_dst, const void* gmem_src) {
    unsigned saddr = (unsigned)__cvta_generic_to_shared(smem_dst);
    asm volatile("cp.async.cg.shared.global [%0], [%1], 16;\n" ::"r"(saddr), "l"(gmem_src));
}
__device__ __forceinline__ void cp_commit() {
    asm volatile("cp.async.commit_group;\n");
}
__device__ __forceinline__ void cp_wait1() {
    asm volatile("cp.async.wait_group 1;\n");
}

__global__ __launch_bounds__(THREADS, 2)
void attn_main_kernel(const float* __restrict__ qg,
                      const float* __restrict__ kg,
                      const float* __restrict__ vg,
                      const float* __restrict__ mg,
                      float* __restrict__ outg,
                      float* __restrict__ attng) {
    extern __shared__ char sm[];
    __half* Qh   = (__half*)(sm + QH_OFF);
    __half* Kh   = (__half*)(sm + KH_OFF);
    __half* Vh   = (__half*)(sm + VH_OFF);
    float*  Psf  = (float*)(sm + PSF_OFF);
    __half* Psh  = (__half*)(sm + PSH_OFF);
    float*  Ms   = (float*)(sm + MS_OFF);    // [2][64 x MLD]
    float*  lrow = (float*)(sm + LROW_OFF);

    const int h  = blockIdx.x;   // fastest: mask slice L2-reused across heads
    const int qt = blockIdx.y;
    const int b  = blockIdx.z;
    const int tid  = threadIdx.x;
    const int warp = tid >> 5;
    const int q0   = qt * TQ;

    const long long bh = (long long)b * Hc + h;
    const float* qptr  = qg + (bh * Sc + q0) * (long long)Dc;
    const float* kbase = kg + bh * Sc * (long long)Dc;
    const float* vbase = vg + bh * Sc * (long long)Dc;
    const float* mbase = mg + ((long long)b * Sc + q0) * (long long)Sc;
    float* attnbase = attng ? (attng + (bh * Sc + q0) * (long long)Sc) : nullptr;

    // ---- Load Q (64x128 fp32 -> fp16 RN) ----
    #pragma unroll
    for (int i = 0; i < 4; ++i) {
        int fid = tid + i * THREADS;       // 0..2047 float4 slots
        int r = fid >> 5, c = (fid & 31) * 4;
        float4 v = *(const float4*)(qptr + (long long)r * Dc + c);
        __half2 h01 = __floats2half2_rn(v.x, v.y);
        __half2 h23 = __floats2half2_rn(v.z, v.w);
        uint2 u; u.x = *(unsigned*)&h01; u.y = *(unsigned*)&h23;
        *(uint2*)(Qh + r * LDH + c) = u;
    }
    if (tid < TQ) lrow[tid] = 0.0f;

    // Prologue: prefetch mask tile 0 into buffer 0 (16 KB)
    {
        int r = tid >> 4, c = (tid & 15) * 4;
        cp_async16(Ms + r * MLD + c, mbase + (long long)r * Sc + c);
        r += 32;
        cp_async16(Ms + r * MLD + c, mbase + (long long)r * Sc + c);
    }
    cp_commit();

    // Warp tiles: scores warp -> (ti, tj) 16x16;  PV warp -> rows ti, cols tj*2..tj*2+1
    const int ti = warp >> 2;        // 0..3
    const int tj = warp & 3;         // 0..3

    wmma::fragment<wmma::accumulator, 16, 16, 16, float> Oacc[2];
    wmma::fill_fragment(Oacc[0], 0.0f);
    wmma::fill_fragment(Oacc[1], 0.0f);

    const int NKT = Sc / TK;
    for (int kt = 0; kt < NKT; ++kt) {
        const int cur = kt & 1;
        const int nxt = cur ^ 1;

        __syncthreads();   // sync1: prev iter's PV reads of Kh/Vh/Psh complete

        // ---- Load K/V tile (fp32 -> fp16 RN), full 64 rows ----
        {
            const float* kp = kbase + (long long)kt * TK * Dc;
            const float* vp = vbase + (long long)kt * TK * Dc;
            float4 kr[4], vr[4];
            #pragma unroll
            for (int i = 0; i < 4; ++i) {
                int fid = tid + i * THREADS;           // 0..2047 float4 slots
                int r = fid >> 5, c = (fid & 31) * 4;  // 32 float4 per 128-float row
                kr[i] = *(const float4*)(kp + (long long)r * Dc + c);
                vr[i] = *(const float4*)(vp + (long long)r * Dc + c);
            }
            #pragma unroll
            for (int i = 0; i < 4; ++i) {
                int fid = tid + i * THREADS;
                int r = fid >> 5, c = (fid & 31) * 4;
                __half2 a0 = __floats2half2_rn(kr[i].x, kr[i].y);
                __half2 a1 = __floats2half2_rn(kr[i].z, kr[i].w);
                uint2 u; u.x = *(unsigned*)&a0; u.y = *(unsigned*)&a1;
                *(uint2*)(Kh + r * LDH + c) = u;
                a0 = __floats2half2_rn(vr[i].x, vr[i].y);
                a1 = __floats2half2_rn(vr[i].z, vr[i].w);
                u.x = *(unsigned*)&a0; u.y = *(unsigned*)&a1;
                *(uint2*)(Vh + r * LDH + c) = u;
            }
        }

        // Prefetch next mask tile into the other buffer
        if (kt + 1 < NKT) {
            const float* mnext = mbase + (long long)(kt + 1) * TK;
            int r = tid >> 4, c = (tid & 15) * 4;
            cp_async16(Ms + nxt * TQ * MLD + r * MLD + c, mnext + (long long)r * Sc + c);
            r += 32;
            cp_async16(Ms + nxt * TQ * MLD + r * MLD + c, mnext + (long long)r * Sc + c);
        }
        cp_commit();  // empty group on last iter is fine

        __syncthreads();   // sync2: Kh/Vh visible

        // ---- Scores: S = Q * K^T (fp16 wmma, fp32 acc) ----
        {
            wmma::fragment<wmma::accumulator, 16, 16, 16, float> Sacc;
            wmma::fill_fragment(Sacc, 0.0f);
            #pragma unroll
            for (int k = 0; k < Dc / 16; ++k) {
                wmma::fragment<wmma::matrix_a, 16, 16, 16, __half, wmma::row_major> af;
                wmma::fragment<wmma::matrix_b, 16, 16, 16, __half, wmma::col_major> bf;
                wmma::load_matrix_sync(af, Qh + ti * 16 * LDH + k * 16, LDH);
                wmma::load_matrix_sync(bf, Kh + tj * 16 * LDH + k * 16, LDH);
                wmma::mma_sync(Sacc, af, bf, Sacc);
            }
            wmma::store_matrix_sync(Psf + ti * 16 * PLDF + tj * 16, Sacc, PLDF,
                                    wmma::mem_row_major);
        }
        cp_wait1();        // mask tile kt (committed last iter / prologue) is in
        __syncthreads();   // sync3: Psf + mask visible

        // ---- Elementwise: p = mask ? 0 : exp(s/128); attn write; rowsum; P->fp16 ----
        {
            const int r  = tid >> 3;          // 0..63
            const int c0 = (tid & 7) * 8;     // 8 cols per thread
            const float* mrow = Ms + cur * TQ * MLD + r * MLD + c0;
            float* arow = attnbase ? attnbase + (long long)r * Sc + kt * TK + c0 : nullptr;
            const float* srow = Psf + r * PLDF + c0;
            float lsum = 0.0f;
            __half2 ph[4];
            #pragma unroll
            for (int cc = 0; cc < 2; ++cc) {
                float4 s4 = *(const float4*)(srow + cc * 4);
                float4 m4 = *(const float4*)(mrow + cc * 4);
                float4 p;
                #pragma unroll
                for (int e = 0; e < 4; ++e) {
                    float x = ((&s4.x)[e]) * 0.0078125f;
                    float pe = 1.388888889e-3f;                 // 1/720
                    pe = fmaf(pe, x, 8.333333333e-3f);           // 1/120
                    pe = fmaf(pe, x, 4.166666667e-2f);           // 1/24
                    pe = fmaf(pe, x, 1.666666667e-1f);           // 1/6
                    pe = fmaf(pe, x, 0.5f);
                    pe = fmaf(pe, x, 1.0f);
                    pe = fmaf(pe, x, 1.0f);
                    if (fabsf(x) > 0.5f) pe = __expf(x);         // ~never taken
                    (&p.x)[e] = ((&m4.x)[e] != 0.0f) ? 0.0f : pe;
                }
                if (arow) *(float4*)(arow + cc * 4) = p;
                lsum += p.x + p.y + p.z + p.w;
                ph[cc * 2 + 0] = __floats2half2_rn(p.x, p.y);
                ph[cc * 2 + 1] = __floats2half2_rn(p.z, p.w);
            }
            uint4 u;
            u.x = *(unsigned*)&ph[0]; u.y = *(unsigned*)&ph[1];
            u.z = *(unsigned*)&ph[2]; u.w = *(unsigned*)&ph[3];
            *(uint4*)(Psh + r * PLDH + c0) = u;

            lsum += __shfl_xor_sync(0xffffffffu, lsum, 1);
            lsum += __shfl_xor_sync(0xffffffffu, lsum, 2);
            lsum += __shfl_xor_sync(0xffffffffu, lsum, 4);
            if ((tid & 7) == 0) lrow[r] += lsum;
        }
        __syncthreads();   // sync4: Psh visible

        // ---- PV: O += P * V (fp16 wmma) ----
        #pragma unroll
        for (int k = 0; k < TK / 16; ++k) {
            wmma::fragment<wmma::matrix_a, 16, 16, 16, __half, wmma::row_major> af;
            wmma::load_matrix_sync(af, Psh + ti * 16 * PLDH + k * 16, PLDH);
            #pragma unroll
            for (int jj = 0; jj < 2; ++jj) {
                wmma::fragment<wmma::matrix_b, 16, 16, 16, __half, wmma::row_major> bf;
                wmma::load_matrix_sync(bf, Vh + k * 16 * LDH + (tj * 2 + jj) * 16, LDH);
                wmma::mma_sync(Oacc[jj], af, bf, Oacc[jj]);
            }
        }
    }

    __syncthreads();
    // Stage O (fp32) into the K+V region, then normalized write
    float* Of = (float*)(sm + KH_OFF);   // 64 x OLDF floats (33,792 B fits K+V 34,816 B)
    #pragma unroll
    for (int jj = 0; jj < 2; ++jj)
        wmma::store_matrix_sync(Of + ti * 16 * OLDF + (tj * 2 + jj) * 16, Oacc[jj],
                                OLDF, wmma::mem_row_major);
    __syncthreads();

    {
        const int r  = tid >> 3;
        const int c0 = (tid & 7) * 16;
        const float inv = 1.0f / lrow[r];
        float* orow = outg + (bh * Sc + q0 + r) * (long long)Dc;
        #pragma unroll
        for (int cc = 0; cc < 4; ++cc) {
            int c = c0 + cc * 4;
            float4 o4 = *(const float4*)(Of + r * OLDF + c);
            o4.x *= inv; o4.y *= inv; o4.z *= inv; o4.w *= inv;
            *(float4*)(orow + c) = o4;
        }
    }
}

// Kernel 2: normalize each attn row in place. Measured ~88% DRAM -> at roofline.
__global__ __launch_bounds__(256, 8)
void attn_norm_kernel(float* __restrict__ attn) {
    const long long row = blockIdx.x;
    float4* rp = (float4*)(attn + row * (long long)Sc);
    const int t = threadIdx.x;

    float4 a = rp[t];
    float4 b = rp[t + 256];
    float s = a.x + a.y + a.z + a.w + b.x + b.y + b.z + b.w;
    #pragma unroll
    for (int o = 16; o > 0; o >>= 1) s += __shfl_xor_sync(0xffffffffu, s, o);

    __shared__ float red[8];
    if ((t & 31) == 0) red[t >> 5] = s;
    __syncthreads();
    float tot = red[0] + red[1] + red[2] + red[3] + red[4] + red[5] + red[6] + red[7];
    float inv = 1.0f / tot;

    a.x *= inv; a.y *= inv; a.z *= inv; a.w *= inv;
    b.x *= inv; b.y *= inv; b.z *= inv; b.w *= inv;
    rp[t] = a;
    rp[t + 256] = b;
}

extern "C" void kernel_launch(void* const* d_in, const int* in_sizes, int n_in,
                              void* d_out, int out_size) {
    const float* q = (const float*)d_in[0];
    const float* k = (const float*)d_in[1];
    const float* v = (const float*)d_in[2];
    const float* m = (const float*)d_in[3];
    float* out = (float*)d_out;

    const long long OUT_ELE = (long long)Bc * Hc * Sc * Dc;  // 16,777,216
    float* attn = ((long long)out_size > OUT_ELE) ? (out + OUT_ELE) : nullptr;

    cudaFuncSetAttribute(attn_main_kernel,
                         cudaFuncAttributeMaxDynamicSharedMemorySize, SMEM_BYTES);
    cudaFuncSetAttribute(attn_main_kernel,
                         cudaFuncAttributePreferredSharedMemoryCarveout, 100);

    dim3 grid1(Hc, Sc / TQ, Bc);  // h fastest -> mask L2 reuse across heads
    attn_main_kernel<<<grid1, THREADS, SMEM_BYTES>>>(q, k, v, m, out, attn);

    if (attn) {
        attn_norm_kernel<<<(long long)Bc * Hc * Sc, 256>>>(attn);
    }
}

// round 7
// speedup vs baseline: 2.1330x; 1.0235x over previous
#include <cuda_runtime.h>
#include <cuda_fp16.h>
#include <mma.h>

using namespace nvcuda;

// Problem constants
#define Bc 4
#define Hc 16
#define Sc 2048
#define Dc 128
#define NTOT (Bc * Hc * Sc * Dc)   // 16,777,216

// Tiling
#define TQ 64
#define TK 64
#define THREADS 512          // 16 warps
#define LDH  136             // half stride for Q/K/V tiles (128 + 8)
#define PLDF 68              // float stride for score tile (64 + 4)
#define PLDH 72              // half stride for P tile (64 + 8)
#define MLD  64              // float stride for mask tile
#define OLDF 132             // float stride for O staging (reuses K+V region)

// smem layout (bytes)
#define QH_OFF   0
#define KH_OFF   (QH_OFF + TQ * LDH * 2)          // 17408
#define VH_OFF   (KH_OFF + TK * LDH * 2)          // 34816
#define PSF_OFF  (VH_OFF + TK * LDH * 2)          // 52224
#define PSH_OFF  (PSF_OFF + TQ * PLDF * 4)        // 69632
#define MS_OFF   (PSH_OFF + TQ * PLDH * 2)        // 78848
#define LROW_OFF (MS_OFF + TQ * MLD * 4)          // 95232
#define SMEM_BYTES (LROW_OFF + TQ * 4)            // 95,488 B -> 2 CTAs/SM

// fp16 copies of Q/K/V (pre-pass output). Static device scratch: allowed.
__device__ __half g_qh[NTOT];
__device__ __half g_kh[NTOT];
__device__ __half g_vh[NTOT];

__device__ __forceinline__ void cp_async16(void* smem_dst, const void* gmem_src) {
    unsigned saddr = (unsigned)__cvta_generic_to_shared(smem_dst);
    asm volatile("cp.async.cg.shared.global [%0], [%1], 16;\n" ::"r"(saddr), "l"(gmem_src));
}
__device__ __forceinline__ void cp_commit() {
    asm volatile("cp.async.commit_group;\n");
}
__device__ __forceinline__ void cp_wait0() {
    asm volatile("cp.async.wait_group 0;\n");
}

// ---- Pre-pass: fp32 -> fp16 RN conversion of Q, K, V ----
__global__ __launch_bounds__(256)
void cvt_kernel(const float4* __restrict__ q,
                const float4* __restrict__ k,
                const float4* __restrict__ v) {
    int i = blockIdx.x * blockDim.x + threadIdx.x;   // 0 .. NTOT/4-1
    float4 a = q[i];
    __half2 h0 = __floats2half2_rn(a.x, a.y);
    __half2 h1 = __floats2half2_rn(a.z, a.w);
    uint2 u; u.x = *(unsigned*)&h0; u.y = *(unsigned*)&h1;
    ((uint2*)g_qh)[i] = u;

    a = k[i];
    h0 = __floats2half2_rn(a.x, a.y);
    h1 = __floats2half2_rn(a.z, a.w);
    u.x = *(unsigned*)&h0; u.y = *(unsigned*)&h1;
    ((uint2*)g_kh)[i] = u;

    a = v[i];
    h0 = __floats2half2_rn(a.x, a.y);
    h1 = __floats2half2_rn(a.z, a.w);
    u.x = *(unsigned*)&h0; u.y = *(unsigned*)&h1;
    ((uint2*)g_vh)[i] = u;
}

__global__ __launch_bounds__(THREADS, 2)
void attn_main_kernel(const float* __restrict__ mg,
                      float* __restrict__ outg,
                      float* __restrict__ attng) {
    extern __shared__ char sm[];
    __half* Qh   = (__half*)(sm + QH_OFF);
    __half* Kh   = (__half*)(sm + KH_OFF);
    __half* Vh   = (__half*)(sm + VH_OFF);
    float*  Psf  = (float*)(sm + PSF_OFF);
    __half* Psh  = (__half*)(sm + PSH_OFF);
    float*  Ms   = (float*)(sm + MS_OFF);
    float*  lrow = (float*)(sm + LROW_OFF);

    const int h  = blockIdx.x;   // fastest: mask slice L2-reused across heads
    const int qt = blockIdx.y;
    const int b  = blockIdx.z;
    const int tid  = threadIdx.x;
    const int warp = tid >> 5;
    const int q0   = qt * TQ;

    const long long bh = (long long)b * Hc + h;
    const __half* qptr  = g_qh + (bh * Sc + q0) * (long long)Dc;
    const __half* kbase = g_kh + bh * Sc * (long long)Dc;
    const __half* vbase = g_vh + bh * Sc * (long long)Dc;
    const float*  mbase = mg + ((long long)b * Sc + q0) * (long long)Sc;
    float* attnbase = attng ? (attng + (bh * Sc + q0) * (long long)Sc) : nullptr;

    // Prologue: cp.async Q tile (fp16, 16 KB). Covered by the loop's first wait.
    {
        int r = tid >> 4, c8 = (tid & 15) * 8;     // 16 x 16B chunks per 128-half row
        cp_async16(Qh + r * LDH + c8, qptr + (long long)r * Dc + c8);
        r += 32;
        cp_async16(Qh + r * LDH + c8, qptr + (long long)r * Dc + c8);
    }
    if (tid < TQ) lrow[tid] = 0.0f;

    // Warp tiles: scores warp -> (ti, tj) 16x16;  PV warp -> rows ti, cols tj*2..tj*2+1
    const int ti = warp >> 2;        // 0..3
    const int tj = warp & 3;         // 0..3

    wmma::fragment<wmma::accumulator, 16, 16, 16, float> Oacc[2];
    wmma::fill_fragment(Oacc[0], 0.0f);
    wmma::fill_fragment(Oacc[1], 0.0f);

    const int NKT = Sc / TK;
    for (int kt = 0; kt < NKT; ++kt) {
        __syncthreads();   // sync1: prev iter's PV reads of Kh/Vh/Psh complete

        // ---- cp.async K/V (fp16 direct) + mask tile ----
        {
            const __half* kp = kbase + (long long)kt * TK * Dc;
            const __half* vp = vbase + (long long)kt * TK * Dc;
            int r = tid >> 4, c8 = (tid & 15) * 8;
            cp_async16(Kh + r * LDH + c8, kp + (long long)r * Dc + c8);
            cp_async16(Vh + r * LDH + c8, vp + (long long)r * Dc + c8);
            r += 32;
            cp_async16(Kh + r * LDH + c8, kp + (long long)r * Dc + c8);
            cp_async16(Vh + r * LDH + c8, vp + (long long)r * Dc + c8);

            const float* mp = mbase + (long long)kt * TK;
            int rm = tid >> 4, cm = (tid & 15) * 4;
            cp_async16(Ms + rm * MLD + cm, mp + (long long)rm * Sc + cm);
            rm += 32;
            cp_async16(Ms + rm * MLD + cm, mp + (long long)rm * Sc + cm);
        }
        cp_commit();
        cp_wait0();
        __syncthreads();   // sync2: Qh/Kh/Vh/Ms visible

        // ---- Scores: S = Q * K^T (fp16 wmma, fp32 acc) ----
        {
            wmma::fragment<wmma::accumulator, 16, 16, 16, float> Sacc;
            wmma::fill_fragment(Sacc, 0.0f);
            #pragma unroll
            for (int k = 0; k < Dc / 16; ++k) {
                wmma::fragment<wmma::matrix_a, 16, 16, 16, __half, wmma::row_major> af;
                wmma::fragment<wmma::matrix_b, 16, 16, 16, __half, wmma::col_major> bf;
                wmma::load_matrix_sync(af, Qh + ti * 16 * LDH + k * 16, LDH);
                wmma::load_matrix_sync(bf, Kh + tj * 16 * LDH + k * 16, LDH);
                wmma::mma_sync(Sacc, af, bf, Sacc);
            }
            wmma::store_matrix_sync(Psf + ti * 16 * PLDF + tj * 16, Sacc, PLDF,
                                    wmma::mem_row_major);
        }
        __syncthreads();   // sync3: Psf visible

        // ---- Elementwise: p = mask ? 0 : exp(s/128); attn write; rowsum; P->fp16 ----
        {
            const int r  = tid >> 3;          // 0..63
            const int c0 = (tid & 7) * 8;     // 8 cols per thread
            const float* mrow = Ms + r * MLD + c0;
            float* arow = attnbase ? attnbase + (long long)r * Sc + kt * TK + c0 : nullptr;
            const float* srow = Psf + r * PLDF + c0;
            float lsum = 0.0f;
            __half2 ph[4];
            #pragma unroll
            for (int cc = 0; cc < 2; ++cc) {
                float4 s4 = *(const float4*)(srow + cc * 4);
                float4 m4 = *(const float4*)(mrow + cc * 4);
                float4 p;
                #pragma unroll
                for (int e = 0; e < 4; ++e) {
                    float x = ((&s4.x)[e]) * 0.0078125f;
                    float pe = 1.388888889e-3f;                 // 1/720
                    pe = fmaf(pe, x, 8.333333333e-3f);           // 1/120
                    pe = fmaf(pe, x, 4.166666667e-2f);           // 1/24
                    pe = fmaf(pe, x, 1.666666667e-1f);           // 1/6
                    pe = fmaf(pe, x, 0.5f);
                    pe = fmaf(pe, x, 1.0f);
                    pe = fmaf(pe, x, 1.0f);
                    if (fabsf(x) > 0.5f) pe = __expf(x);         // ~never taken
                    (&p.x)[e] = ((&m4.x)[e] != 0.0f) ? 0.0f : pe;
                }
                if (arow) *(float4*)(arow + cc * 4) = p;
                lsum += p.x + p.y + p.z + p.w;
                ph[cc * 2 + 0] = __floats2half2_rn(p.x, p.y);
                ph[cc * 2 + 1] = __floats2half2_rn(p.z, p.w);
            }
            uint4 u;
            u.x = *(unsigned*)&ph[0]; u.y = *(unsigned*)&ph[1];
            u.z = *(unsigned*)&ph[2]; u.w = *(unsigned*)&ph[3];
            *(uint4*)(Psh + r * PLDH + c0) = u;

            lsum += __shfl_xor_sync(0xffffffffu, lsum, 1);
            lsum += __shfl_xor_sync(0xffffffffu, lsum, 2);
            lsum += __shfl_xor_sync(0xffffffffu, lsum, 4);
            if ((tid & 7) == 0) lrow[r] += lsum;
        }
        __syncthreads();   // sync4: Psh visible

        // ---- PV: O += P * V (fp16 wmma) ----
        #pragma unroll
        for (int k = 0; k < TK / 16; ++k) {
            wmma::fragment<wmma::matrix_a, 16, 16, 16, __half, wmma::row_major> af;
            wmma::load_matrix_sync(af, Psh + ti * 16 * PLDH + k * 16, PLDH);
            #pragma unroll
            for (int jj = 0; jj < 2; ++jj) {
                wmma::fragment<wmma::matrix_b, 16, 16, 16, __half, wmma::row_major> bf;
                wmma::load_matrix_sync(bf, Vh + k * 16 * LDH + (tj * 2 + jj) * 16, LDH);
                wmma::mma_sync(Oacc[jj], af, bf, Oacc[jj]);
            }
        }
    }

    __syncthreads();
    // Stage O (fp32) into the K+V region, then normalized write
    float* Of = (float*)(sm + KH_OFF);   // 64 x OLDF floats (33,792 B fits K+V 34,816 B)
    #pragma unroll
    for (int jj = 0; jj < 2; ++jj)
        wmma::store_matrix_sync(Of + ti * 16 * OLDF + (tj * 2 + jj) * 16, Oacc[jj],
                                OLDF, wmma::mem_row_major);
    __syncthreads();

    {
        const int r  = tid >> 3;
        const int c0 = (tid & 7) * 16;
        const float inv = 1.0f / lrow[r];
        float* orow = outg + (bh * Sc + q0 + r) * (long long)Dc;
        #pragma unroll
        for (int cc = 0; cc < 4; ++cc) {
            int c = c0 + cc * 4;
            float4 o4 = *(const float4*)(Of + r * OLDF + c);
            o4.x *= inv; o4.y *= inv; o4.z *= inv; o4.w *= inv;
            *(float4*)(orow + c) = o4;
        }
    }
}

// Kernel 2: normalize each attn row in place. Measured ~88% DRAM -> at roofline.
__global__ __launch_bounds__(256, 8)
void attn_norm_kernel(float* __restrict__ attn) {
    const long long row = blockIdx.x;
    float4* rp = (float4*)(attn + row * (long long)Sc);
    const int t = threadIdx.x;

    float4 a = rp[t];
    float4 b = rp[t + 256];
    float s = a.x + a.y + a.z + a.w + b.x + b.y + b.z + b.w;
    #pragma unroll
    for (int o = 16; o > 0; o >>= 1) s += __shfl_xor_sync(0xffffffffu, s, o);

    __shared__ float red[8];
    if ((t & 31) == 0) red[t >> 5] = s;
    __syncthreads();
    float tot = red[0] + red[1] + red[2] + red[3] + red[4] + red[5] + red[6] + red[7];
    float inv = 1.0f / tot;

    a.x *= inv; a.y *= inv; a.z *= inv; a.w *= inv;
    b.x *= inv; b.y *= inv; b.z *= inv; b.w *= inv;
    rp[t] = a;
    rp[t + 256] = b;
}

extern "C" void kernel_launch(void* const* d_in, const int* in_sizes, int n_in,
                              void* d_out, int out_size) {
    const float* q = (const float*)d_in[0];
    const float* k = (const float*)d_in[1];
    const float* v = (const float*)d_in[2];
    const float* m = (const float*)d_in[3];
    float* out = (float*)d_out;

    const long long OUT_ELE = (long long)Bc * Hc * Sc * Dc;  // 16,777,216
    float* attn = ((long long)out_size > OUT_ELE) ? (out + OUT_ELE) : nullptr;

    cudaFuncSetAttribute(attn_main_kernel,
                         cudaFuncAttributeMaxDynamicSharedMemorySize, SMEM_BYTES);
    cudaFuncSetAttribute(attn_main_kernel,
                         cudaFuncAttributePreferredSharedMemoryCarveout, 100);

    // Pre-pass: fp32 -> fp16 for Q/K/V (grid-stride free: exact cover)
    cvt_kernel<<<NTOT / 4 / 256, 256>>>((const float4*)q, (const float4*)k,
                                        (const float4*)v);

    dim3 grid1(Hc, Sc / TQ, Bc);  // h fastest -> mask L2 reuse across heads
    attn_main_kernel<<<grid1, THREADS, SMEM_BYTES>>>(m, out, attn);

    if (attn) {
        attn_norm_kernel<<<(long long)Bc * Hc * Sc, 256>>>(attn);
    }
}